// round 3
// baseline (speedup 1.0000x reference)
#include <cuda_runtime.h>
#include <cstdint>

#define NB    128
#define NPRI  32768
#define TOPK  400
#define KEEPK 200
#define T     512
#define WORDS 13
#define CONF_T 0.5f
#define NMS_T  0.5f
#define BIGNEG -1000000000.0f
#define NBINS 8192
#define BLK1  16
#define CH    (NPRI / BLK1)

__device__ unsigned           g_score[NB * NPRI];   // ordered-float score bits
__device__ unsigned long long g_cand[NB * NPRI];    // gathered candidate keys
__device__ unsigned           g_hist[NB * NBINS];
__device__ int                g_ccnt[NB];
__device__ unsigned           g_binv[NB];

__device__ __forceinline__ unsigned order_f(float f) {
    unsigned u = __float_as_uint(f);
    return (u & 0x80000000u) ? ~u : (u | 0x80000000u);
}
__device__ __forceinline__ float unorder_f(unsigned u) {
    unsigned v = (u & 0x80000000u) ? (u ^ 0x80000000u) : ~u;
    return __uint_as_float(v);
}

// ---------------------------------------------------------------- K0: zero
__global__ void k0_zero() {
    int i = blockIdx.x * blockDim.x + threadIdx.x;
    if (i < NB * NBINS) g_hist[i] = 0;
    if (i < NB) g_ccnt[i] = 0;
}

// ------------------------------------------- K1: scores + 13-bit histogram
__global__ __launch_bounds__(T) void k1_score(const float* __restrict__ pred) {
    const int b   = blockIdx.x / BLK1;
    const int seg = blockIdx.x % BLK1;
    const float* P = pred + (size_t)b * NPRI * 6;
    const int base = seg * CH;

    float2 c[CH / T];
    #pragma unroll
    for (int k = 0; k < CH / T; k++) {
        int i = base + k * T + threadIdx.x;
        c[k] = *reinterpret_cast<const float2*>(P + 6 * i + 4);
    }
    #pragma unroll
    for (int k = 0; k < CH / T; k++) {
        int i = base + k * T + threadIdx.x;
        float s = fmaxf(c[k].x, c[k].y);
        float m = (s > CONF_T) ? s : BIGNEG;
        unsigned u = order_f(m);
        g_score[(size_t)b * NPRI + i] = u;
        if (s > CONF_T) atomicAdd(&g_hist[b * NBINS + (u >> 19)], 1u);
    }
}

// ------------------------------------------------- K2: per-image threshold
__global__ __launch_bounds__(256) void k2_thresh() {
    __shared__ unsigned sh[NBINS];
    __shared__ unsigned part[256];
    const int b = blockIdx.x, tid = threadIdx.x;
    for (int i = tid; i < NBINS; i += 256) sh[i] = g_hist[b * NBINS + i];
    __syncthreads();
    unsigned sum = 0;
    #pragma unroll 4
    for (int j = 0; j < 32; j++) sum += sh[tid * 32 + ((j + tid) & 31)];
    part[tid] = sum;
    __syncthreads();
    if (tid == 0) {
        unsigned acc = 0;
        int seg = 255;
        for (; seg >= 0; --seg) {
            if (acc + part[seg] >= TOPK) break;
            acc += part[seg];
        }
        unsigned binv = 0;
        if (seg >= 0) {
            int bbase = seg * 32, bi = 31;
            for (; bi >= 0; --bi) {
                if (acc + sh[bbase + bi] >= TOPK) break;
                acc += sh[bbase + bi];
            }
            binv = (unsigned)(bbase + bi);
        }
        g_binv[b] = binv;           // 0 => accept-all fallback (npass < 400)
    }
}

// -------------------------------------------------------- K2a: gather cands
__global__ __launch_bounds__(T) void k2a_gather() {
    const int b   = blockIdx.x / BLK1;
    const int seg = blockIdx.x % BLK1;
    const unsigned thr = g_binv[b] << 19;
    const unsigned* sc = g_score + (size_t)b * NPRI;
    unsigned long long* cand = g_cand + (size_t)b * NPRI;
    const int lane = threadIdx.x & 31;
    const int base = seg * CH;
    #pragma unroll
    for (int k = 0; k < CH / T; k++) {
        int i = base + k * T + threadIdx.x;
        unsigned u = sc[i];
        bool p = (u >= thr);
        unsigned mask = __ballot_sync(0xffffffffu, p);
        if (mask) {
            int leader = __ffs(mask) - 1;
            int bp = 0;
            if (lane == leader) bp = atomicAdd(&g_ccnt[b], __popc(mask));
            bp = __shfl_sync(0xffffffffu, bp, leader);
            if (p) {
                int off = bp + __popc(mask & ((1u << lane) - 1u));
                cand[off] = ((unsigned long long)u << 32) |
                            (unsigned)(0xFFFFFFFFu - (unsigned)i);
            }
        }
    }
}

// ------------------------------------------------ K3: sort + NMS + output
__global__ __launch_bounds__(T)
void k3_nms(const float* __restrict__ pred,
            const float* __restrict__ priors,
            float* __restrict__ out) {
    const int b    = blockIdx.x;
    const int tid  = threadIdx.x;
    const int lane = tid & 31;
    const int wid  = tid >> 5;
    const float* P = pred + (size_t)b * NPRI * 6;
    unsigned long long* cand = g_cand + (size_t)b * NPRI;

    __shared__ unsigned hist[256];
    __shared__ unsigned long long s_top[512];
    __shared__ float s_x1[TOPK], s_y1[TOPK], s_x2[TOPK], s_y2[TOPK];
    __shared__ float s_ar[TOPK], s_sc[TOPK];
    __shared__ int   s_lab[TOPK];
    __shared__ unsigned s_sup[TOPK * WORDS];
    __shared__ unsigned s_keep[WORDS];
    __shared__ int s_n, s_nkeep, s_krem;
    __shared__ unsigned long long s_pv;

    const int cnt = g_ccnt[b];

    if (cnt <= 512) {
        // Normal path: candidates fit; sort them all.
        s_top[tid] = (tid < cnt) ? cand[tid] : 0ull;
        __syncthreads();
    } else {
        // Exact fallback: radix-select the 400th-largest key over cand[0..cnt)
        if (tid == 0) { s_pv = 0ull; s_krem = TOPK; }
        __syncthreads();
        for (int byt = 7; byt >= 0; --byt) {
            for (int i = tid; i < 256; i += T) hist[i] = 0;
            __syncthreads();
            unsigned long long pv = s_pv;
            unsigned long long hb =
                (byt == 7) ? 0ull : (0xFFFFFFFFFFFFFFFFull << ((byt + 1) * 8));
            for (int i = tid; i < cnt; i += T) {
                unsigned long long e = cand[i];
                if (((e ^ pv) & hb) == 0)
                    atomicAdd(&hist[(unsigned)((e >> (byt * 8)) & 255)], 1u);
            }
            __syncthreads();
            if (tid == 0) {
                unsigned acc = 0;
                int d = 255;
                for (; d >= 0; --d) {
                    if (acc + hist[d] >= (unsigned)s_krem) break;
                    acc += hist[d];
                }
                s_krem -= (int)acc;
                s_pv |= ((unsigned long long)(unsigned)d) << (byt * 8);
            }
            __syncthreads();
        }
        unsigned long long kth = s_pv;
        if (tid == 0) s_n = 0;
        __syncthreads();
        for (int i = tid; i < cnt; i += T) {
            unsigned long long e = cand[i];
            if (e >= kth) {
                int p = atomicAdd(&s_n, 1);
                if (p < 512) s_top[p] = e;
            }
        }
        __syncthreads();
        int n = s_n;
        if (tid >= n) s_top[tid] = 0ull;
        __syncthreads();
    }

    // ----- bitonic sort 512 DESC -----
    for (int ksz = 2; ksz <= 512; ksz <<= 1)
        for (int j = ksz >> 1; j > 0; j >>= 1) {
            int ixj = tid ^ j;
            if (ixj > tid) {
                unsigned long long a = s_top[tid], c = s_top[ixj];
                bool sw = ((tid & ksz) == 0) ? (a < c) : (a > c);
                if (sw) { s_top[tid] = c; s_top[ixj] = a; }
            }
            __syncthreads();
        }

    // ----- decode candidate boxes -----
    if (tid < TOPK) {
        unsigned long long key = s_top[tid];
        unsigned u = (unsigned)(key >> 32);
        float sc = unorder_f(u);
        int idx = (int)(0xFFFFFFFFu - (unsigned)(key & 0xFFFFFFFFull));
        s_sc[tid] = sc;
        const float* pp = P + 6 * idx;
        float l0 = pp[0], l1 = pp[1], l2 = pp[2], l3 = pp[3];
        float c0 = pp[4], c1 = pp[5];
        float4 pr = *reinterpret_cast<const float4*>(priors + 4 * idx);
        float cx = __fadd_rn(pr.x, __fmul_rn(__fmul_rn(l0, 0.1f), pr.z));
        float cy = __fadd_rn(pr.y, __fmul_rn(__fmul_rn(l1, 0.1f), pr.w));
        float w  = __fmul_rn(pr.z, expf(__fmul_rn(l2, 0.2f)));
        float h  = __fmul_rn(pr.w, expf(__fmul_rn(l3, 0.2f)));
        float x1 = __fsub_rn(cx, __fmul_rn(w, 0.5f));
        float y1 = __fsub_rn(cy, __fmul_rn(h, 0.5f));
        float x2 = __fadd_rn(cx, __fmul_rn(w, 0.5f));
        float y2 = __fadd_rn(cy, __fmul_rn(h, 0.5f));
        s_x1[tid] = x1; s_y1[tid] = y1; s_x2[tid] = x2; s_y2[tid] = y2;
        s_ar[tid] = __fmul_rn(__fsub_rn(x2, x1), __fsub_rn(y2, y1));
        s_lab[tid] = (c1 > c0) ? 1 : 0;
    }
    __syncthreads();

    // ----- suppression bitmask via ballots -----
    {
        const int NW = T / 32;
        for (int task = wid; task < TOPK * WORDS; task += NW) {
            int i = task / WORDS;
            int w = task - i * WORDS;
            int j = w * 32 + lane;
            bool sbit = false;
            if (j < TOPK && j > i) {
                float iw = fmaxf(__fsub_rn(fminf(s_x2[i], s_x2[j]),
                                           fmaxf(s_x1[i], s_x1[j])), 0.0f);
                float ih = fmaxf(__fsub_rn(fminf(s_y2[i], s_y2[j]),
                                           fmaxf(s_y1[i], s_y1[j])), 0.0f);
                float inter = __fmul_rn(iw, ih);
                float den = __fadd_rn(__fsub_rn(__fadd_rn(s_ar[i], s_ar[j]), inter),
                                      1e-12f);
                sbit = (__fdiv_rn(inter, den) > NMS_T);
            }
            unsigned wd = __ballot_sync(0xffffffffu, sbit);
            if (lane == 0) s_sup[task] = wd;
        }
    }
    if (tid < WORDS * 32) {
        bool v = (tid < TOPK) && (s_sc[tid] > CONF_T);
        unsigned m = __ballot_sync(0xffffffffu, v);
        if (lane == 0) s_keep[wid] = m;
    }
    __syncthreads();

    // ----- greedy NMS (single thread, bit-skip) -----
    if (tid == 0) {
        unsigned kp[WORDS];
        #pragma unroll
        for (int w = 0; w < WORDS; w++) kp[w] = s_keep[w];
        int i = 0;
        while (i < TOPK) {
            int wi = i >> 5;
            unsigned m = kp[wi] & (0xFFFFFFFFu << (i & 31));
            if (!m) { i = (wi + 1) << 5; continue; }
            i = (wi << 5) + (__ffs(m) - 1);
            const unsigned* row = &s_sup[i * WORDS];
            #pragma unroll
            for (int w = 0; w < WORDS; w++) kp[w] &= ~row[w];
            i++;
        }
        int nk = 0;
        #pragma unroll
        for (int w = 0; w < WORDS; w++) { s_keep[w] = kp[w]; nk += __popc(kp[w]); }
        s_nkeep = nk;
    }
    __syncthreads();

    // ----- stable ascending sort of kept -----
    {
        int i = tid;
        unsigned long long key2 = ~0ull;
        bool kept = (i < TOPK) && ((s_keep[i >> 5] >> (i & 31)) & 1u);
        if (kept) {
            unsigned u = order_f(s_sc[i]);
            key2 = ((unsigned long long)u << 32) | (unsigned)i;
        }
        s_top[i] = key2;
    }
    __syncthreads();
    for (int ksz = 2; ksz <= 512; ksz <<= 1)
        for (int j = ksz >> 1; j > 0; j >>= 1) {
            int ixj = tid ^ j;
            if (ixj > tid) {
                unsigned long long a = s_top[tid], c = s_top[ixj];
                bool sw = ((tid & ksz) == 0) ? (a > c) : (a < c);
                if (sw) { s_top[tid] = c; s_top[ixj] = a; }
            }
            __syncthreads();
        }

    // ----- emit -----
    {
        float* ob = out + (size_t)b * (KEEPK * 6);
        int nk = min(s_nkeep, KEEPK);
        for (int r = tid; r < KEEPK; r += T) {
            float o0 = 0.f, o1 = 0.f, o2 = 0.f, o3 = 0.f, o4 = 0.f, o5 = 0.f;
            if (r < nk) {
                int pos = (int)(s_top[r] & 0xFFFFFFFFull);
                o0 = (float)s_lab[pos];
                o1 = s_sc[pos];
                o2 = s_x1[pos]; o3 = s_y1[pos];
                o4 = s_x2[pos]; o5 = s_y2[pos];
            }
            ob[r * 6 + 0] = o0; ob[r * 6 + 1] = o1; ob[r * 6 + 2] = o2;
            ob[r * 6 + 3] = o3; ob[r * 6 + 4] = o4; ob[r * 6 + 5] = o5;
        }
    }
}

extern "C" void kernel_launch(void* const* d_in, const int* in_sizes, int n_in,
                              void* d_out, int out_size) {
    const float* pred   = (const float*)d_in[0];
    const float* priors = (const float*)d_in[1];
    int nb = in_sizes[0] / (NPRI * 6);
    if (nb <= 0 || nb > NB) nb = NB;
    k0_zero<<<(NB * NBINS + 255) / 256, 256>>>();
    k1_score<<<nb * BLK1, T>>>(pred);
    k2_thresh<<<nb, 256>>>();
    k2a_gather<<<nb * BLK1, T>>>();
    k3_nms<<<nb, T>>>(pred, priors, (float*)d_out);
}

// round 5
// speedup vs baseline: 1.5923x; 1.5923x over previous
#include <cuda_runtime.h>
#include <cstdint>

#define NB    128
#define NPRI  32768
#define TOPK  400
#define KEEPK 200
#define T     512
#define WORDS 13
#define CONF_T 0.5f
#define NMS_T  0.5f
#define BIGNEG -1000000000.0f
#define HBINS 512
#define HBASE 12224u          // order_f(0.5) >> 18
#define SEGS  16
#define SEGBOX (NPRI / SEGS)  // 2048 boxes per k1 block

__device__ unsigned           g_score[NB * NPRI];
__device__ unsigned long long g_cand[NB * NPRI];
__device__ unsigned           g_hist[NB * HBINS];   // zero-init at load; k3 re-zeros

__device__ __forceinline__ unsigned order_f(float f) {
    unsigned u = __float_as_uint(f);
    return (u & 0x80000000u) ? ~u : (u | 0x80000000u);
}
__device__ __forceinline__ float unorder_f(unsigned u) {
    unsigned v = (u & 0x80000000u) ? (u ^ 0x80000000u) : ~u;
    return __uint_as_float(v);
}

// ============ K1: stream pred, emit ordered scores + 512-bin histogram ======
__global__ __launch_bounds__(256)
void k1_score(const float* __restrict__ pred) {
    const int b   = blockIdx.x >> 4;      // image
    const int seg = blockIdx.x & 15;
    __shared__ unsigned sh[HBINS];
    sh[threadIdx.x] = 0; sh[threadIdx.x + 256] = 0;
    __syncthreads();

    const float4* P4 = reinterpret_cast<const float4*>(
        pred + (size_t)b * NPRI * 6 + (size_t)seg * SEGBOX * 6);
    uint2* S2 = reinterpret_cast<uint2*>(g_score + (size_t)b * NPRI + seg * SEGBOX);

    #pragma unroll
    for (int it = 0; it < 4; it++) {
        int e = it * 256 + threadIdx.x;       // box-pair index in segment
        float4 a1 = P4[3 * e + 1];
        float4 a2 = P4[3 * e + 2];
        float s0 = fmaxf(a1.x, a1.y);         // conf of box 2e
        float s1 = fmaxf(a2.z, a2.w);         // conf of box 2e+1
        unsigned u0 = order_f((s0 > CONF_T) ? s0 : BIGNEG);
        unsigned u1 = order_f((s1 > CONF_T) ? s1 : BIGNEG);
        S2[e] = make_uint2(u0, u1);
        if (s0 > CONF_T) atomicAdd(&sh[min(511u, (u0 >> 18) - HBASE)], 1u);
        if (s1 > CONF_T) atomicAdd(&sh[min(511u, (u1 >> 18) - HBASE)], 1u);
    }
    __syncthreads();
    #pragma unroll
    for (int i = threadIdx.x; i < HBINS; i += 256) {
        unsigned v = sh[i];
        if (v) atomicAdd(&g_hist[b * HBINS + i], v);
    }
}

// ============ K3: threshold + gather + sort + NMS + emit =====================
__global__ __launch_bounds__(T)
void k3_nms(const float* __restrict__ pred,
            const float* __restrict__ priors,
            float* __restrict__ out) {
    const int b    = blockIdx.x;
    const int tid  = threadIdx.x;
    const int lane = tid & 31;
    const int wid  = tid >> 5;
    const float* P = pred + (size_t)b * NPRI * 6;
    unsigned long long* cand = g_cand + (size_t)b * NPRI;

    __shared__ unsigned s_ss[HBINS];         // suffix-scan, then radix hist
    __shared__ unsigned long long s_top[512];
    __shared__ float s_x1[TOPK], s_y1[TOPK], s_x2[TOPK], s_y2[TOPK];
    __shared__ float s_ar[TOPK], s_sc[TOPK];
    __shared__ int   s_lab[TOPK];
    __shared__ unsigned s_sup[TOPK * WORDS];
    __shared__ unsigned s_keep[WORDS];
    __shared__ int s_n, s_nkeep, s_krem, s_v;
    __shared__ unsigned long long s_pv;

    // ---- load + reset histogram, suffix-scan for threshold bin ----
    s_ss[tid] = g_hist[b * HBINS + tid];
    g_hist[b * HBINS + tid] = 0;             // reset for next graph replay
    if (tid == 0) { s_n = 0; s_v = 0; }
    __syncthreads();
    #pragma unroll
    for (int d = 1; d < HBINS; d <<= 1) {
        unsigned v = (tid + d < HBINS) ? s_ss[tid + d] : 0u;
        __syncthreads();
        s_ss[tid] += v;
        __syncthreads();
    }
    {
        bool hit = (s_ss[tid] >= TOPK) && (tid == HBINS - 1 || s_ss[tid + 1] < TOPK);
        if (hit) s_v = tid;
    }
    __syncthreads();
    const unsigned thr = (HBASE + (unsigned)s_v) << 18;

    // ---- gather candidates (warp-aggregated shared counter) ----
    {
        const uint4* S4 = reinterpret_cast<const uint4*>(g_score + (size_t)b * NPRI);
        #pragma unroll 4
        for (int k = 0; k < NPRI / (4 * T); k++) {
            uint4 v = S4[k * T + tid];
            unsigned base_i = (unsigned)(k * T + tid) * 4u;
            #pragma unroll
            for (int e = 0; e < 4; e++) {
                unsigned u = (e == 0) ? v.x : (e == 1) ? v.y : (e == 2) ? v.z : v.w;
                bool p = (u >= thr);
                unsigned mask = __ballot_sync(0xffffffffu, p);
                if (mask) {
                    int leader = __ffs(mask) - 1;
                    int bp = 0;
                    if (lane == leader) bp = atomicAdd(&s_n, __popc(mask));
                    bp = __shfl_sync(0xffffffffu, bp, leader);
                    if (p) {
                        int off = bp + __popc(mask & ((1u << lane) - 1u));
                        if (off < NPRI)
                            cand[off] = ((unsigned long long)u << 32) |
                                        (0xFFFFFFFFu - (base_i + e));
                    }
                }
            }
        }
    }
    __syncthreads();
    const int cnt = s_n;

    if (cnt <= 512) {
        s_top[tid] = (tid < cnt) ? cand[tid] : 0ull;
        __syncthreads();
    } else {
        // exact radix-select of 400th-largest over cand[0..cnt)
        if (tid == 0) { s_pv = 0ull; s_krem = TOPK; }
        __syncthreads();
        for (int byt = 7; byt >= 0; --byt) {
            for (int i = tid; i < 256; i += T) s_ss[i] = 0;
            __syncthreads();
            unsigned long long pv = s_pv;
            unsigned long long hb =
                (byt == 7) ? 0ull : (0xFFFFFFFFFFFFFFFFull << ((byt + 1) * 8));
            for (int i = tid; i < cnt; i += T) {
                unsigned long long e = cand[i];
                if (((e ^ pv) & hb) == 0)
                    atomicAdd(&s_ss[(unsigned)((e >> (byt * 8)) & 255)], 1u);
            }
            __syncthreads();
            if (tid == 0) {
                unsigned acc = 0; int d = 255;
                for (; d >= 0; --d) {
                    if (acc + s_ss[d] >= (unsigned)s_krem) break;
                    acc += s_ss[d];
                }
                s_krem -= (int)acc;
                s_pv |= ((unsigned long long)(unsigned)d) << (byt * 8);
            }
            __syncthreads();
        }
        unsigned long long kth = s_pv;
        if (tid == 0) s_n = 0;
        __syncthreads();
        for (int i = tid; i < cnt; i += T) {
            unsigned long long e = cand[i];
            if (e >= kth) {
                int p = atomicAdd(&s_n, 1);
                if (p < 512) s_top[p] = e;
            }
        }
        __syncthreads();
        int n = s_n;
        if (tid >= n) s_top[tid] = 0ull;
        __syncthreads();
    }

    // ---- bitonic sort 512 DESC ----
    for (int ksz = 2; ksz <= 512; ksz <<= 1)
        for (int j = ksz >> 1; j > 0; j >>= 1) {
            int ixj = tid ^ j;
            if (ixj > tid) {
                unsigned long long a = s_top[tid], c = s_top[ixj];
                bool sw = ((tid & ksz) == 0) ? (a < c) : (a > c);
                if (sw) { s_top[tid] = c; s_top[ixj] = a; }
            }
            __syncthreads();
        }

    // ---- decode candidate boxes ----
    if (tid < TOPK) {
        unsigned long long key = s_top[tid];
        unsigned u = (unsigned)(key >> 32);
        float sc = unorder_f(u);
        unsigned idxu = 0xFFFFFFFFu - (unsigned)(key & 0xFFFFFFFFull);
        int idx = (int)min(idxu, (unsigned)(NPRI - 1));   // safe for pad keys
        s_sc[tid] = sc;
        const float* pp = P + 6 * idx;
        float l0 = pp[0], l1 = pp[1], l2 = pp[2], l3 = pp[3];
        float c0 = pp[4], c1 = pp[5];
        float4 pr = *reinterpret_cast<const float4*>(priors + 4 * idx);
        float cx = __fadd_rn(pr.x, __fmul_rn(__fmul_rn(l0, 0.1f), pr.z));
        float cy = __fadd_rn(pr.y, __fmul_rn(__fmul_rn(l1, 0.1f), pr.w));
        float w  = __fmul_rn(pr.z, expf(__fmul_rn(l2, 0.2f)));
        float h  = __fmul_rn(pr.w, expf(__fmul_rn(l3, 0.2f)));
        float x1 = __fsub_rn(cx, __fmul_rn(w, 0.5f));
        float y1 = __fsub_rn(cy, __fmul_rn(h, 0.5f));
        float x2 = __fadd_rn(cx, __fmul_rn(w, 0.5f));
        float y2 = __fadd_rn(cy, __fmul_rn(h, 0.5f));
        s_x1[tid] = x1; s_y1[tid] = y1; s_x2[tid] = x2; s_y2[tid] = y2;
        s_ar[tid] = __fmul_rn(__fsub_rn(x2, x1), __fsub_rn(y2, y1));
        s_lab[tid] = (c1 > c0) ? 1 : 0;
    }
    __syncthreads();

    // ---- suppression bitmask via ballots ----
    {
        const int NW = T / 32;
        for (int task = wid; task < TOPK * WORDS; task += NW) {
            int i = task / WORDS;
            int w = task - i * WORDS;
            int j = w * 32 + lane;
            bool sbit = false;
            if (j < TOPK && j > i) {
                float iw = fmaxf(__fsub_rn(fminf(s_x2[i], s_x2[j]),
                                           fmaxf(s_x1[i], s_x1[j])), 0.0f);
                float ih = fmaxf(__fsub_rn(fminf(s_y2[i], s_y2[j]),
                                           fmaxf(s_y1[i], s_y1[j])), 0.0f);
                float inter = __fmul_rn(iw, ih);
                float den = __fadd_rn(__fsub_rn(__fadd_rn(s_ar[i], s_ar[j]), inter),
                                      1e-12f);
                sbit = (__fdiv_rn(inter, den) > NMS_T);
            }
            unsigned wd = __ballot_sync(0xffffffffu, sbit);
            if (lane == 0) s_sup[task] = wd;
        }
    }
    if (tid < WORDS * 32) {
        bool v = (tid < TOPK) && (s_sc[tid] > CONF_T);
        unsigned m = __ballot_sync(0xffffffffu, v);
        if (lane == 0) s_keep[wid] = m;
    }
    __syncthreads();

    // ---- greedy NMS (single thread, bit-skip) ----
    if (tid == 0) {
        unsigned kp[WORDS];
        #pragma unroll
        for (int w = 0; w < WORDS; w++) kp[w] = s_keep[w];
        int i = 0;
        while (i < TOPK) {
            int wi = i >> 5;
            unsigned m = kp[wi] & (0xFFFFFFFFu << (i & 31));
            if (!m) { i = (wi + 1) << 5; continue; }
            i = (wi << 5) + (__ffs(m) - 1);
            const unsigned* row = &s_sup[i * WORDS];
            #pragma unroll
            for (int w = 0; w < WORDS; w++) kp[w] &= ~row[w];
            i++;
        }
        int nk = 0;
        #pragma unroll
        for (int w = 0; w < WORDS; w++) { s_keep[w] = kp[w]; nk += __popc(kp[w]); }
        s_nkeep = nk;
    }
    __syncthreads();

    // ---- stable ascending sort of kept ----
    {
        int i = tid;
        unsigned long long key2 = ~0ull;
        bool kept = (i < TOPK) && ((s_keep[i >> 5] >> (i & 31)) & 1u);
        if (kept) {
            unsigned u = order_f(s_sc[i]);
            key2 = ((unsigned long long)u << 32) | (unsigned)i;
        }
        s_top[i] = key2;
    }
    __syncthreads();
    for (int ksz = 2; ksz <= 512; ksz <<= 1)
        for (int j = ksz >> 1; j > 0; j >>= 1) {
            int ixj = tid ^ j;
            if (ixj > tid) {
                unsigned long long a = s_top[tid], c = s_top[ixj];
                bool sw = ((tid & ksz) == 0) ? (a > c) : (a < c);
                if (sw) { s_top[tid] = c; s_top[ixj] = a; }
            }
            __syncthreads();
        }

    // ---- emit ----
    {
        float* ob = out + (size_t)b * (KEEPK * 6);
        int nk = min(s_nkeep, KEEPK);
        for (int r = tid; r < KEEPK; r += T) {
            float o0 = 0.f, o1 = 0.f, o2 = 0.f, o3 = 0.f, o4 = 0.f, o5 = 0.f;
            if (r < nk) {
                int pos = (int)(s_top[r] & 0xFFFFFFFFull);
                o0 = (float)s_lab[pos];
                o1 = s_sc[pos];
                o2 = s_x1[pos]; o3 = s_y1[pos];
                o4 = s_x2[pos]; o5 = s_y2[pos];
            }
            ob[r * 6 + 0] = o0; ob[r * 6 + 1] = o1; ob[r * 6 + 2] = o2;
            ob[r * 6 + 3] = o3; ob[r * 6 + 4] = o4; ob[r * 6 + 5] = o5;
        }
    }
}

extern "C" void kernel_launch(void* const* d_in, const int* in_sizes, int n_in,
                              void* d_out, int out_size) {
    const float* pred   = (const float*)d_in[0];
    const float* priors = (const float*)d_in[1];
    int nb = in_sizes[0] / (NPRI * 6);
    if (nb <= 0 || nb > NB) nb = NB;
    k1_score<<<nb * SEGS, 256>>>(pred);
    k3_nms<<<nb, T>>>(pred, priors, (float*)d_out);
}